// round 14
// baseline (speedup 1.0000x reference)
#include <cuda_runtime.h>

#define NN 100000
#define EE 3200000
#define FIN 512
#define HID 16
#define CC 40
#define NB 391          // ceil(NN/256) scan blocks

// ---------------- scratch (static device globals) -----------------------------
__device__ float  g_deg[NN];
__device__ float  g_dis[NN];
__device__ int    g_cnt[NN];
__device__ int    g_base[NN];      // exclusive scan; mutated to row-ends by scatter
__device__ int    g_bsum[NB];
__device__ int    g_bsumx[NB];
__device__ unsigned long long g_wz[256 * 16];  // W1 k-pair-zipped: [k/2][f]
__device__ int2   g_edge[EE];      // dest-sorted (src, norm-as-int)
__device__ float4 g_h1p[2 * NN * 4]; // K-split partial products of x@W1
__device__ float4 g_h1[NN * 4];    // h1 = x@W1, [N,16] as [N,4] float4
__device__ float4 g_agg1[NN * 4];  // layer-1 aggregation
__device__ float4 g_agg2[NN * 4];  // layer-2 aggregation (16-dim, pre-W2)

#define FMA2(d, a, b) asm("fma.rn.f32x2 %0, %1, %2, %0;" : "+l"(d) : "l"(a), "l"(b))
#define ZIP(d, a, b)  asm("mov.b64 %0, {%1, %2};" : "=l"(d) : "f"(a), "f"(b))
#define CPA16(s, g)   asm volatile("cp.async.cg.shared.global [%0], [%1], 16;" :: "r"(s), "l"(g))
#define CP_COMMIT()   asm volatile("cp.async.commit_group;")
#define CP_WAIT(n)    asm volatile("cp.async.wait_group %0;" :: "n"(n))

// ---------------- zero init ---------------------------------------------------
__global__ void zero_kernel() {
    int i = blockIdx.x * blockDim.x + threadIdx.x;
    if (i < NN) { g_cnt[i] = 0; g_deg[i] = 0.f; }
}

// ---------------- in-degree count + weighted degree ---------------------------
__global__ void count_kernel(const int* __restrict__ ei,
                             const float* __restrict__ w) {
    int e = blockIdx.x * blockDim.x + threadIdx.x;
    if (e >= EE) return;
    int c = ei[EE + e];
    atomicAdd(&g_cnt[c], 1);
    atomicAdd(&g_deg[c], w[e]);
}

// ---------------- W1 zip: g_wz[k2*16+f] = (W1[2k2][f], W1[2k2+1][f]) ----------
__global__ void wzip_kernel(const float* __restrict__ W1) {
    int i = blockIdx.x * blockDim.x + threadIdx.x;
    if (i >= 256 * 16) return;
    int k2 = i >> 4, f = i & 15;
    unsigned long long z;
    ZIP(z, W1[(2 * k2) * 16 + f], W1[(2 * k2 + 1) * 16 + f]);
    g_wz[i] = z;
}

// ---------------- 3-kernel exclusive scan of g_cnt -> g_base ------------------
__global__ void scanA_kernel() {
    __shared__ int s[256];
    int tid = threadIdx.x;
    int i = blockIdx.x * 256 + tid;
    int v = (i < NN) ? g_cnt[i] : 0;
    s[tid] = v;
    __syncthreads();
    for (int off = 1; off < 256; off <<= 1) {
        int t = (tid >= off) ? s[tid - off] : 0;
        __syncthreads();
        s[tid] += t;
        __syncthreads();
    }
    if (i < NN) g_base[i] = s[tid] - v;          // exclusive, intra-block
    if (tid == 255) g_bsum[blockIdx.x] = s[255];
}

__global__ void scanB_kernel() {
    __shared__ int s[512];
    int tid = threadIdx.x;
    int v = (tid < NB) ? g_bsum[tid] : 0;
    s[tid] = v;
    __syncthreads();
    for (int off = 1; off < 512; off <<= 1) {
        int t = (tid >= off) ? s[tid - off] : 0;
        __syncthreads();
        s[tid] += t;
        __syncthreads();
    }
    if (tid < NB) g_bsumx[tid] = s[tid] - v;     // exclusive block offsets
}

__global__ void scanC_kernel() {
    int i = blockIdx.x * blockDim.x + threadIdx.x;
    if (i < NN) g_base[i] += g_bsumx[i >> 8];
}

// ---------------- scatter edges (src, norm); bumps g_base to row-end ----------
__global__ void scatter_kernel(const int* __restrict__ ei,
                               const float* __restrict__ w) {
    int e = blockIdx.x * blockDim.x + threadIdx.x;
    if (e >= EE) return;
    int r = ei[e];
    int c = ei[EE + e];
    float nw = g_dis[r] * w[e] * g_dis[c];
    int pos = atomicAdd(&g_base[c], 1);
    g_edge[pos] = make_int2(r, __float_as_int(nw));
}

// ---------------- GEMM1 v8: 256 thr, 4n x 4f tile, K split over blockIdx.y ----
// 64 ng x 4 fg; lane = 4*(ng&7)+fg -> fg lanes adjacent (smem broadcast free);
// pitch-5-f4 rows; W pre-zipped k-pairs; 2-stage cp.async; K=256 per half.
#define KCH 16
#define NCHUNK_H (FIN / 2 / KCH)   // 16 chunks per half
__global__ void __launch_bounds__(256) gemm1_kernel(const float* __restrict__ x) {
    __shared__ float4 xs[2][256 * 5];                 // [stage][node*5 + kq]
    __shared__ unsigned long long wsm[2][8 * 16];     // [stage][kp*16 + f]
    int tid = threadIdx.x;
    int warp = tid >> 5;
    int lane = tid & 31;
    int fg = lane & 3;                   // f = 4fg .. 4fg+3
    int ng = warp * 8 + (lane >> 2);     // 0..63
    int nodeBase = blockIdx.x * 256;
    int half = blockIdx.y;               // 0 or 1
    int kbase = half * (FIN / 2);        // 0 or 256

    // cp.async coords: 1024 x-f4 per stage, 256 threads -> 4 each
    int xnl = tid >> 2;                  // node-local base (plus 64*s)
    int xkq = tid & 3;

    unsigned long long acc[4][4];
#pragma unroll
    for (int i = 0; i < 4; ++i)
#pragma unroll
        for (int f = 0; f < 4; ++f) acc[i][f] = 0ull;

    const float* xg = x + (size_t)kbase + (size_t)xkq * 4;

#define LOAD_CHUNK(kc, buf)                                                        \
    {                                                                              \
        int kb_ = (kc) * KCH;                                                      \
        _Pragma("unroll")                                                          \
        for (int s_ = 0; s_ < 4; ++s_) {                                           \
            int nl_ = xnl + 64 * s_;                                               \
            int node_ = nodeBase + nl_; if (node_ >= NN) node_ = NN - 1;           \
            unsigned d_ = (unsigned)__cvta_generic_to_shared(&xs[buf][nl_ * 5 + xkq]); \
            CPA16(d_, xg + (size_t)node_ * FIN + kb_);                             \
        }                                                                          \
        if (tid < 64) {                                                            \
            unsigned dw_ = (unsigned)__cvta_generic_to_shared(&wsm[buf][tid * 2]); \
            CPA16(dw_, &g_wz[half * 2048 + (kc) * 128 + tid * 2]);                 \
        }                                                                          \
        CP_COMMIT();                                                               \
    }

    LOAD_CHUNK(0, 0)

    for (int kc = 0; kc < NCHUNK_H; ++kc) {
        int cur = kc & 1;
        if (kc + 1 < NCHUNK_H) {
            LOAD_CHUNK(kc + 1, cur ^ 1)
            CP_WAIT(1);
        } else {
            CP_WAIT(0);
        }
        __syncthreads();

#pragma unroll
        for (int kq = 0; kq < 4; ++kq) {
            // k-pairs kp0 = 2kq (k = 4kq,4kq+1), kp1 = 2kq+1 (k = 4kq+2,4kq+3)
            ulonglong2 w0a = *(const ulonglong2*)&wsm[cur][(2 * kq) * 16 + 4 * fg];
            ulonglong2 w0b = *(const ulonglong2*)&wsm[cur][(2 * kq) * 16 + 4 * fg + 2];
            ulonglong2 w1a = *(const ulonglong2*)&wsm[cur][(2 * kq + 1) * 16 + 4 * fg];
            ulonglong2 w1b = *(const ulonglong2*)&wsm[cur][(2 * kq + 1) * 16 + 4 * fg + 2];
#pragma unroll
            for (int i = 0; i < 4; ++i) {
                ulonglong2 xu = *(const ulonglong2*)&xs[cur][(ng + 64 * i) * 5 + kq];
                FMA2(acc[i][0], xu.x, w0a.x);
                FMA2(acc[i][1], xu.x, w0a.y);
                FMA2(acc[i][2], xu.x, w0b.x);
                FMA2(acc[i][3], xu.x, w0b.y);
                FMA2(acc[i][0], xu.y, w1a.x);
                FMA2(acc[i][1], xu.y, w1a.y);
                FMA2(acc[i][2], xu.y, w1b.x);
                FMA2(acc[i][3], xu.y, w1b.y);
            }
        }
        __syncthreads();
    }

    // fold k-split halves; one float4 store per node (f = 4fg..4fg+3)
    float4* dst = g_h1p + (size_t)half * NN * 4;
#pragma unroll
    for (int i = 0; i < 4; ++i) {
        int node = nodeBase + ng + 64 * i;
        if (node >= NN) continue;
        float lo, hi;
        float4 o;
        asm("mov.b64 {%0, %1}, %2;" : "=f"(lo), "=f"(hi) : "l"(acc[i][0])); o.x = lo + hi;
        asm("mov.b64 {%0, %1}, %2;" : "=f"(lo), "=f"(hi) : "l"(acc[i][1])); o.y = lo + hi;
        asm("mov.b64 {%0, %1}, %2;" : "=f"(lo), "=f"(hi) : "l"(acc[i][2])); o.z = lo + hi;
        asm("mov.b64 {%0, %1}, %2;" : "=f"(lo), "=f"(hi) : "l"(acc[i][3])); o.w = lo + hi;
        dst[node * 4 + fg] = o;
    }
}

// ---------------- combine K-split partials + dis ------------------------------
__global__ void combine_kernel() {
    int i = blockIdx.x * blockDim.x + threadIdx.x;
    if (i < NN * 4) {
        float4 a = g_h1p[i];
        float4 b = g_h1p[NN * 4 + i];
        g_h1[i] = make_float4(a.x + b.x, a.y + b.y, a.z + b.z, a.w + b.w);
    }
    if (i < NN) {
        float d = g_deg[i];
        g_dis[i] = (d > 0.f) ? rsqrtf(d) : 0.f;
    }
}

// ---------------- gather-reduce propagation (warp per node, no atomics) -------
__global__ void __launch_bounds__(256) gather1_kernel() {
    int node = (blockIdx.x * 256 + threadIdx.x) >> 5;
    if (node >= NN) return;
    int lane = threadIdx.x & 31;
    int q = lane & 3;
    int es = lane >> 2;
    int b0 = node ? g_base[node - 1] : 0;
    int b1e = g_base[node];
    float4 acc = make_float4(0.f, 0.f, 0.f, 0.f);
    for (int i = b0 + es; i < b1e; i += 8) {
        int2 ew = g_edge[i];
        float nw = __int_as_float(ew.y);
        float4 v = g_h1[ew.x * 4 + q];
        acc.x += nw * v.x; acc.y += nw * v.y;
        acc.z += nw * v.z; acc.w += nw * v.w;
    }
#pragma unroll
    for (int m = 16; m >= 4; m >>= 1) {
        acc.x += __shfl_xor_sync(0xffffffffu, acc.x, m);
        acc.y += __shfl_xor_sync(0xffffffffu, acc.y, m);
        acc.z += __shfl_xor_sync(0xffffffffu, acc.z, m);
        acc.w += __shfl_xor_sync(0xffffffffu, acc.w, m);
    }
    if (es == 0) g_agg1[node * 4 + q] = acc;
}

// layer 2: gather relu(agg1[src] + b1) * norm
__global__ void __launch_bounds__(256) gather2_kernel(const float* __restrict__ b1) {
    int node = (blockIdx.x * 256 + threadIdx.x) >> 5;
    if (node >= NN) return;
    int lane = threadIdx.x & 31;
    int q = lane & 3;
    int es = lane >> 2;
    float4 b = ((const float4*)b1)[q];
    int b0 = node ? g_base[node - 1] : 0;
    int b1e = g_base[node];
    float4 acc = make_float4(0.f, 0.f, 0.f, 0.f);
    for (int i = b0 + es; i < b1e; i += 8) {
        int2 ew = g_edge[i];
        float nw = __int_as_float(ew.y);
        float4 v = g_agg1[ew.x * 4 + q];
        acc.x += nw * fmaxf(v.x + b.x, 0.f);
        acc.y += nw * fmaxf(v.y + b.y, 0.f);
        acc.z += nw * fmaxf(v.z + b.z, 0.f);
        acc.w += nw * fmaxf(v.w + b.w, 0.f);
    }
#pragma unroll
    for (int m = 16; m >= 4; m >>= 1) {
        acc.x += __shfl_xor_sync(0xffffffffu, acc.x, m);
        acc.y += __shfl_xor_sync(0xffffffffu, acc.y, m);
        acc.z += __shfl_xor_sync(0xffffffffu, acc.z, m);
        acc.w += __shfl_xor_sync(0xffffffffu, acc.w, m);
    }
    if (es == 0) g_agg2[node * 4 + q] = acc;
}

// ---------------- epilogue: out = log_softmax(agg2 @ W2 + b2) -----------------
__global__ void __launch_bounds__(256) out_kernel(const float* __restrict__ W2,
                                                  const float* __restrict__ b2,
                                                  float* __restrict__ out) {
    __shared__ float w2s[HID * CC];
    __shared__ float b2s[CC];
    int tid = threadIdx.x;
    for (int i = tid; i < HID * CC; i += 256) w2s[i] = W2[i];
    if (tid < CC) b2s[tid] = b2[tid];
    __syncthreads();

    int n = blockIdx.x * blockDim.x + tid;
    if (n >= NN) return;

    float a[16];
    float4* ap = (float4*)a;
    ap[0] = g_agg2[n * 4 + 0];
    ap[1] = g_agg2[n * 4 + 1];
    ap[2] = g_agg2[n * 4 + 2];
    ap[3] = g_agg2[n * 4 + 3];

    float logit[CC];
    float mx = -1e30f;
#pragma unroll
    for (int j = 0; j < CC; ++j) {
        float s = b2s[j];
#pragma unroll
        for (int i = 0; i < 16; ++i) s += a[i] * w2s[i * CC + j];
        logit[j] = s;
        mx = fmaxf(mx, s);
    }
    float sum = 0.f;
#pragma unroll
    for (int j = 0; j < CC; ++j) sum += expf(logit[j] - mx);
    float lse = mx + logf(sum);
#pragma unroll
    for (int j = 0; j < CC; ++j) out[(size_t)n * CC + j] = logit[j] - lse;
}

// ---------------- launch ------------------------------------------------------
extern "C" void kernel_launch(void* const* d_in, const int* in_sizes, int n_in,
                              void* d_out, int out_size) {
    const float* x  = (const float*)d_in[0];
    const int*   ei = (const int*)d_in[1];
    const float* w  = (const float*)d_in[2];
    const float* W1 = (const float*)d_in[3];
    const float* b1 = (const float*)d_in[4];
    const float* W2 = (const float*)d_in[5];
    const float* b2 = (const float*)d_in[6];
    float*       out = (float*)d_out;

    zero_kernel<<<(NN + 255) / 256, 256>>>();
    count_kernel<<<(EE + 255) / 256, 256>>>(ei, w);
    wzip_kernel<<<16, 256>>>(W1);
    gemm1_kernel<<<dim3((NN + 255) / 256, 2), 256>>>(x);  // 4th launch -> profiled
    combine_kernel<<<(NN * 4 + 255) / 256, 256>>>();
    scanA_kernel<<<NB, 256>>>();
    scanB_kernel<<<1, 512>>>();
    scanC_kernel<<<(NN + 255) / 256, 256>>>();
    scatter_kernel<<<(EE + 255) / 256, 256>>>(ei, w);
    gather1_kernel<<<(NN * 32 + 255) / 256, 256>>>();
    gather2_kernel<<<(NN * 32 + 255) / 256, 256>>>(b1);
    out_kernel<<<(NN + 255) / 256, 256>>>(W2, b2, out);
}

// round 16
// speedup vs baseline: 1.0395x; 1.0395x over previous
#include <cuda_runtime.h>

#define NN 100000
#define EE 3200000
#define FIN 512
#define HID 16
#define CC 40
#define NB 391          // ceil(NN/256) scan blocks

// ---------------- scratch (static device globals) -----------------------------
__device__ float  g_deg[NN];
__device__ float  g_dis[NN];
__device__ int    g_cnt[NN];
__device__ int    g_base[NN];      // exclusive scan; mutated to row-ends by scatter
__device__ int    g_bsum[NB];
__device__ int    g_bsumx[NB];
__device__ unsigned long long g_wz[256 * 16];  // W1 k-pair-zipped: [k/2][f]
__device__ int2   g_edge[EE];      // dest-sorted (src, norm-as-int)
__device__ float4 g_h1p[2 * NN * 4]; // K-split partial products of x@W1
__device__ float4 g_h1[NN * 4];    // h1 = x@W1, [N,16] as [N,4] float4
__device__ float4 g_agg1[NN * 4];  // layer-1 aggregation

#define FMA2(d, a, b) asm("fma.rn.f32x2 %0, %1, %2, %0;" : "+l"(d) : "l"(a), "l"(b))
#define ZIP(d, a, b)  asm("mov.b64 %0, {%1, %2};" : "=l"(d) : "f"(a), "f"(b))
#define CPA16(s, g)   asm volatile("cp.async.cg.shared.global [%0], [%1], 16;" :: "r"(s), "l"(g))
#define CP_COMMIT()   asm volatile("cp.async.commit_group;")
#define CP_WAIT(n)    asm volatile("cp.async.wait_group %0;" :: "n"(n))

// ---------------- zero init ---------------------------------------------------
__global__ void zero_kernel() {
    int i = blockIdx.x * blockDim.x + threadIdx.x;
    if (i < NN) { g_cnt[i] = 0; g_deg[i] = 0.f; }
}

// ---------------- in-degree count + weighted degree ---------------------------
__global__ void count_kernel(const int* __restrict__ ei,
                             const float* __restrict__ w) {
    int e = blockIdx.x * blockDim.x + threadIdx.x;
    if (e >= EE) return;
    int c = ei[EE + e];
    atomicAdd(&g_cnt[c], 1);
    atomicAdd(&g_deg[c], w[e]);
}

// ---------------- W1 zip: g_wz[k2*16+f] = (W1[2k2][f], W1[2k2+1][f]) ----------
__global__ void wzip_kernel(const float* __restrict__ W1) {
    int i = blockIdx.x * blockDim.x + threadIdx.x;
    if (i >= 256 * 16) return;
    int k2 = i >> 4, f = i & 15;
    unsigned long long z;
    ZIP(z, W1[(2 * k2) * 16 + f], W1[(2 * k2 + 1) * 16 + f]);
    g_wz[i] = z;
}

// ---------------- 3-kernel exclusive scan of g_cnt -> g_base ------------------
__global__ void scanA_kernel() {
    __shared__ int s[256];
    int tid = threadIdx.x;
    int i = blockIdx.x * 256 + tid;
    int v = (i < NN) ? g_cnt[i] : 0;
    s[tid] = v;
    __syncthreads();
    for (int off = 1; off < 256; off <<= 1) {
        int t = (tid >= off) ? s[tid - off] : 0;
        __syncthreads();
        s[tid] += t;
        __syncthreads();
    }
    if (i < NN) g_base[i] = s[tid] - v;          // exclusive, intra-block
    if (tid == 255) g_bsum[blockIdx.x] = s[255];
}

__global__ void scanB_kernel() {
    __shared__ int s[512];
    int tid = threadIdx.x;
    int v = (tid < NB) ? g_bsum[tid] : 0;
    s[tid] = v;
    __syncthreads();
    for (int off = 1; off < 512; off <<= 1) {
        int t = (tid >= off) ? s[tid - off] : 0;
        __syncthreads();
        s[tid] += t;
        __syncthreads();
    }
    if (tid < NB) g_bsumx[tid] = s[tid] - v;     // exclusive block offsets
}

__global__ void scanC_kernel() {
    int i = blockIdx.x * blockDim.x + threadIdx.x;
    if (i < NN) g_base[i] += g_bsumx[i >> 8];
}

// ---------------- scatter edges (src, norm); bumps g_base to row-end ----------
__global__ void scatter_kernel(const int* __restrict__ ei,
                               const float* __restrict__ w) {
    int e = blockIdx.x * blockDim.x + threadIdx.x;
    if (e >= EE) return;
    int r = ei[e];
    int c = ei[EE + e];
    float nw = g_dis[r] * w[e] * g_dis[c];
    int pos = atomicAdd(&g_base[c], 1);
    g_edge[pos] = make_int2(r, __float_as_int(nw));
}

// ---------------- GEMM1 (R13 measured-best): K split over blockIdx.y ----------
// 128 thr = 32 ng x 4 fg, 256-node tile, thread 8n x 4f, broadcast lane map,
// pitch-5-f4. Each block handles K/2 = 256 (16 chunks) per blockIdx.y half.
#define KCH 16
#define NCHUNK_H (FIN / 2 / KCH)   // 16 chunks per half
__global__ void __launch_bounds__(128) gemm1_kernel(const float* __restrict__ x) {
    __shared__ float4 xs[2][256 * 5];                 // [stage][node*5 + kq]
    __shared__ unsigned long long wsm[2][8 * 16];     // [stage][kp*16 + f]
    int tid = threadIdx.x;
    int warp = tid >> 5;
    int lane = tid & 31;
    int fg = lane & 3;                   // f = 4fg .. 4fg+3
    int ng = warp * 8 + (lane >> 2);     // 0..31
    int nodeBase = blockIdx.x * 256;
    int half = blockIdx.y;               // 0 or 1
    int kbase = half * (FIN / 2);        // 0 or 256

    // cp.async coords: 1024 x-f4 per stage, 128 threads -> 8 each
    int xnl = tid >> 2;                  // node-local base (plus 32*s)
    int xkq = tid & 3;

    unsigned long long acc[8][4];
#pragma unroll
    for (int i = 0; i < 8; ++i)
#pragma unroll
        for (int f = 0; f < 4; ++f) acc[i][f] = 0ull;

    const float* xg = x + (size_t)kbase + (size_t)xkq * 4;

#define LOAD_CHUNK(kc, buf)                                                        \
    {                                                                              \
        int kb_ = (kc) * KCH;                                                      \
        _Pragma("unroll")                                                          \
        for (int s_ = 0; s_ < 8; ++s_) {                                           \
            int nl_ = xnl + 32 * s_;                                               \
            int node_ = nodeBase + nl_; if (node_ >= NN) node_ = NN - 1;           \
            unsigned d_ = (unsigned)__cvta_generic_to_shared(&xs[buf][nl_ * 5 + xkq]); \
            CPA16(d_, xg + (size_t)node_ * FIN + kb_);                             \
        }                                                                          \
        if (tid < 64) {                                                            \
            unsigned dw_ = (unsigned)__cvta_generic_to_shared(&wsm[buf][tid * 2]); \
            CPA16(dw_, &g_wz[half * 2048 + (kc) * 128 + tid * 2]);                 \
        }                                                                          \
        CP_COMMIT();                                                               \
    }

    LOAD_CHUNK(0, 0)

    for (int kc = 0; kc < NCHUNK_H; ++kc) {
        int cur = kc & 1;
        if (kc + 1 < NCHUNK_H) {
            LOAD_CHUNK(kc + 1, cur ^ 1)
            CP_WAIT(1);
        } else {
            CP_WAIT(0);
        }
        __syncthreads();

#pragma unroll
        for (int kq = 0; kq < 4; ++kq) {
            // k-pairs kp0 = 2kq (k = 4kq,4kq+1), kp1 = 2kq+1 (k = 4kq+2,4kq+3)
            ulonglong2 w0a = *(const ulonglong2*)&wsm[cur][(2 * kq) * 16 + 4 * fg];
            ulonglong2 w0b = *(const ulonglong2*)&wsm[cur][(2 * kq) * 16 + 4 * fg + 2];
            ulonglong2 w1a = *(const ulonglong2*)&wsm[cur][(2 * kq + 1) * 16 + 4 * fg];
            ulonglong2 w1b = *(const ulonglong2*)&wsm[cur][(2 * kq + 1) * 16 + 4 * fg + 2];
#pragma unroll
            for (int i = 0; i < 8; ++i) {
                ulonglong2 xu = *(const ulonglong2*)&xs[cur][(ng + 32 * i) * 5 + kq];
                FMA2(acc[i][0], xu.x, w0a.x);
                FMA2(acc[i][1], xu.x, w0a.y);
                FMA2(acc[i][2], xu.x, w0b.x);
                FMA2(acc[i][3], xu.x, w0b.y);
                FMA2(acc[i][0], xu.y, w1a.x);
                FMA2(acc[i][1], xu.y, w1a.y);
                FMA2(acc[i][2], xu.y, w1b.x);
                FMA2(acc[i][3], xu.y, w1b.y);
            }
        }
        __syncthreads();
    }

    // fold k-split halves; one float4 store per node (f = 4fg..4fg+3)
    float4* dst = g_h1p + (size_t)half * NN * 4;
#pragma unroll
    for (int i = 0; i < 8; ++i) {
        int node = nodeBase + ng + 32 * i;
        if (node >= NN) continue;
        float lo, hi;
        float4 o;
        asm("mov.b64 {%0, %1}, %2;" : "=f"(lo), "=f"(hi) : "l"(acc[i][0])); o.x = lo + hi;
        asm("mov.b64 {%0, %1}, %2;" : "=f"(lo), "=f"(hi) : "l"(acc[i][1])); o.y = lo + hi;
        asm("mov.b64 {%0, %1}, %2;" : "=f"(lo), "=f"(hi) : "l"(acc[i][2])); o.z = lo + hi;
        asm("mov.b64 {%0, %1}, %2;" : "=f"(lo), "=f"(hi) : "l"(acc[i][3])); o.w = lo + hi;
        dst[node * 4 + fg] = o;
    }
}

// ---------------- combine K-split partials + dis ------------------------------
__global__ void combine_kernel() {
    int i = blockIdx.x * blockDim.x + threadIdx.x;
    if (i < NN * 4) {
        float4 a = g_h1p[i];
        float4 b = g_h1p[NN * 4 + i];
        g_h1[i] = make_float4(a.x + b.x, a.y + b.y, a.z + b.z, a.w + b.w);
    }
    if (i < NN) {
        float d = g_deg[i];
        g_dis[i] = (d > 0.f) ? rsqrtf(d) : 0.f;
    }
}

// ---------------- gather-reduce propagation (warp per node, no atomics) -------
__global__ void __launch_bounds__(256) gather1_kernel() {
    int node = (blockIdx.x * 256 + threadIdx.x) >> 5;
    if (node >= NN) return;
    int lane = threadIdx.x & 31;
    int q = lane & 3;
    int es = lane >> 2;
    int b0 = node ? g_base[node - 1] : 0;
    int b1e = g_base[node];
    float4 acc = make_float4(0.f, 0.f, 0.f, 0.f);
    for (int i = b0 + es; i < b1e; i += 8) {
        int2 ew = g_edge[i];
        float nw = __int_as_float(ew.y);
        float4 v = g_h1[ew.x * 4 + q];
        acc.x += nw * v.x; acc.y += nw * v.y;
        acc.z += nw * v.z; acc.w += nw * v.w;
    }
#pragma unroll
    for (int m = 16; m >= 4; m >>= 1) {
        acc.x += __shfl_xor_sync(0xffffffffu, acc.x, m);
        acc.y += __shfl_xor_sync(0xffffffffu, acc.y, m);
        acc.z += __shfl_xor_sync(0xffffffffu, acc.z, m);
        acc.w += __shfl_xor_sync(0xffffffffu, acc.w, m);
    }
    if (es == 0) g_agg1[node * 4 + q] = acc;
}

// ---------------- fused layer-2 gather + W2 + log_softmax ---------------------
// Warp per node: gather relu(agg1[src]+b1)*nw, es-reduce, broadcast the 16-dim
// aggregate via shfl, compute 40 logits from smem W2, warp softmax, store out.
// Grid is exactly NN*32/256 blocks -> no partial blocks.
__global__ void __launch_bounds__(256) gather2out_kernel(const float* __restrict__ b1,
                                                         const float* __restrict__ W2,
                                                         const float* __restrict__ b2,
                                                         float* __restrict__ out) {
    __shared__ float w2s[HID * CC];
    __shared__ float b2s[CC];
    int tid = threadIdx.x;
    for (int i = tid; i < HID * CC; i += 256) w2s[i] = W2[i];
    if (tid < CC) b2s[tid] = b2[tid];
    __syncthreads();

    int node = (blockIdx.x * 256 + tid) >> 5;
    int lane = tid & 31;
    int q = lane & 3;
    int es = lane >> 2;
    float4 b = ((const float4*)b1)[q];
    int b0 = node ? g_base[node - 1] : 0;
    int b1e = g_base[node];
    float4 acc = make_float4(0.f, 0.f, 0.f, 0.f);
    for (int i = b0 + es; i < b1e; i += 8) {
        int2 ew = g_edge[i];
        float nw = __int_as_float(ew.y);
        float4 v = g_agg1[ew.x * 4 + q];
        acc.x += nw * fmaxf(v.x + b.x, 0.f);
        acc.y += nw * fmaxf(v.y + b.y, 0.f);
        acc.z += nw * fmaxf(v.z + b.z, 0.f);
        acc.w += nw * fmaxf(v.w + b.w, 0.f);
    }
#pragma unroll
    for (int m = 16; m >= 4; m >>= 1) {
        acc.x += __shfl_xor_sync(0xffffffffu, acc.x, m);
        acc.y += __shfl_xor_sync(0xffffffffu, acc.y, m);
        acc.z += __shfl_xor_sync(0xffffffffu, acc.z, m);
        acc.w += __shfl_xor_sync(0xffffffffu, acc.w, m);
    }
    // lanes 0..3 hold agg2 quarter q = lane; broadcast all 16 dims warp-wide
    float a[16];
#pragma unroll
    for (int j = 0; j < 4; ++j) {
        a[4 * j + 0] = __shfl_sync(0xffffffffu, acc.x, j);
        a[4 * j + 1] = __shfl_sync(0xffffffffu, acc.y, j);
        a[4 * j + 2] = __shfl_sync(0xffffffffu, acc.z, j);
        a[4 * j + 3] = __shfl_sync(0xffffffffu, acc.w, j);
    }
    // logits: lane c and (lanes 0..7) 32+c
    float l0 = b2s[lane];
#pragma unroll
    for (int i = 0; i < 16; ++i) l0 += a[i] * w2s[i * CC + lane];
    float l1 = -1e30f;
    if (lane < 8) {
        l1 = b2s[32 + lane];
#pragma unroll
        for (int i = 0; i < 16; ++i) l1 += a[i] * w2s[i * CC + 32 + lane];
    }
    float mx = fmaxf(l0, l1);
#pragma unroll
    for (int m = 16; m >= 1; m >>= 1) mx = fmaxf(mx, __shfl_xor_sync(0xffffffffu, mx, m));
    float s = expf(l0 - mx) + ((lane < 8) ? expf(l1 - mx) : 0.f);
#pragma unroll
    for (int m = 16; m >= 1; m >>= 1) s += __shfl_xor_sync(0xffffffffu, s, m);
    float lse = mx + logf(s);
    out[(size_t)node * CC + lane] = l0 - lse;
    if (lane < 8) out[(size_t)node * CC + 32 + lane] = l1 - lse;
}

// ---------------- launch ------------------------------------------------------
extern "C" void kernel_launch(void* const* d_in, const int* in_sizes, int n_in,
                              void* d_out, int out_size) {
    const float* x  = (const float*)d_in[0];
    const int*   ei = (const int*)d_in[1];
    const float* w  = (const float*)d_in[2];
    const float* W1 = (const float*)d_in[3];
    const float* b1 = (const float*)d_in[4];
    const float* W2 = (const float*)d_in[5];
    const float* b2 = (const float*)d_in[6];
    float*       out = (float*)d_out;

    zero_kernel<<<(NN + 255) / 256, 256>>>();
    count_kernel<<<(EE + 255) / 256, 256>>>(ei, w);
    wzip_kernel<<<16, 256>>>(W1);
    gemm1_kernel<<<dim3((NN + 255) / 256, 2), 128>>>(x);  // 4th launch -> profiled
    combine_kernel<<<(NN * 4 + 255) / 256, 256>>>();
    scanA_kernel<<<NB, 256>>>();
    scanB_kernel<<<1, 512>>>();
    scanC_kernel<<<(NN + 255) / 256, 256>>>();
    scatter_kernel<<<(EE + 255) / 256, 256>>>(ei, w);
    gather1_kernel<<<(NN * 32 + 255) / 256, 256>>>();
    gather2out_kernel<<<(NN * 32 + 255) / 256, 256>>>(b1, W2, b2, out);
}

// round 17
// speedup vs baseline: 1.1279x; 1.0851x over previous
#include <cuda_runtime.h>

#define NN 100000
#define EE 3200000
#define FIN 512
#define HID 16
#define CC 40
#define NB 391          // ceil(NN/256) scan blocks

// ---------------- scratch (static device globals) -----------------------------
__device__ float  g_deg[NN];
__device__ float  g_dis[NN];
__device__ int    g_cnt[NN];
__device__ int    g_base[NN];      // exclusive scan; mutated to row-ends by scatter
__device__ int    g_bsum[NB];
__device__ int    g_bsumx[NB];
__device__ unsigned long long g_wz[256 * 16];  // W1 k-pair-zipped: [k/2][f]
__device__ int2   g_edge[EE];      // dest-sorted (src, norm-as-int)
__device__ float4 g_h1p[2 * NN * 4]; // K-split partial products of x@W1
__device__ float4 g_h1[NN * 4];    // h1 = x@W1, [N,16] as [N,4] float4
__device__ float4 g_agg1[NN * 4];  // layer-1 aggregation

#define FMA2(d, a, b) asm("fma.rn.f32x2 %0, %1, %2, %0;" : "+l"(d) : "l"(a), "l"(b))
#define ZIP(d, a, b)  asm("mov.b64 %0, {%1, %2};" : "=l"(d) : "f"(a), "f"(b))
#define CPA16(s, g)   asm volatile("cp.async.cg.shared.global [%0], [%1], 16;" :: "r"(s), "l"(g))
#define CP_COMMIT()   asm volatile("cp.async.commit_group;")
#define CP_WAIT(n)    asm volatile("cp.async.wait_group %0;" :: "n"(n))

// ---------------- zero init + W1 zip ------------------------------------------
__global__ void zerowzip_kernel(const float* __restrict__ W1) {
    int i = blockIdx.x * blockDim.x + threadIdx.x;
    if (i < NN) { g_cnt[i] = 0; g_deg[i] = 0.f; }
    if (i < 256 * 16) {
        int k2 = i >> 4, f = i & 15;
        unsigned long long z;
        ZIP(z, W1[(2 * k2) * 16 + f], W1[(2 * k2 + 1) * 16 + f]);
        g_wz[i] = z;
    }
}

// ---------------- MEGA: gemm1 (even blocks) + count (odd blocks) --------------
// gemm1 part = R13/R16 measured-best: 128 thr = 32 ng x 4 fg, 256-node tile,
// thread 8n x 4f, broadcast lane map, pitch-5-f4, K split in halves.
// count part: grid-stride over edges, 2 atomics each (in-degree + weighted deg).
// Interleaved even/odd so each SM hosts a mix: count's atomic traffic hides in
// gemm1's DRAM-wait shadow.
#define KCH 16
#define NCHUNK_H (FIN / 2 / KCH)   // 16 chunks per half
#define CSTRIDE (782 * 128)
__global__ void __launch_bounds__(128) mega_kernel(const float* __restrict__ x,
                                                   const int* __restrict__ ei,
                                                   const float* __restrict__ w) {
    __shared__ float4 xs[2][256 * 5];                 // [stage][node*5 + kq]
    __shared__ unsigned long long wsm[2][8 * 16];     // [stage][kp*16 + f]
    int b = blockIdx.x;
    if (b & 1) {
        // ---- count role ----
        int base = (b >> 1) * 128 + threadIdx.x;
        for (int e = base; e < EE; e += CSTRIDE) {
            int c = ei[EE + e];
            atomicAdd(&g_cnt[c], 1);
            atomicAdd(&g_deg[c], w[e]);
        }
        return;
    }
    // ---- gemm role: g in [0,782) ----
    int g = b >> 1;
    int half = (g >= 391) ? 1 : 0;
    int bx = half ? (g - 391) : g;
    int tid = threadIdx.x;
    int warp = tid >> 5;
    int lane = tid & 31;
    int fg = lane & 3;                   // f = 4fg .. 4fg+3
    int ng = warp * 8 + (lane >> 2);     // 0..31
    int nodeBase = bx * 256;
    int kbase = half * (FIN / 2);        // 0 or 256

    int xnl = tid >> 2;                  // node-local base (plus 32*s)
    int xkq = tid & 3;

    unsigned long long acc[8][4];
#pragma unroll
    for (int i = 0; i < 8; ++i)
#pragma unroll
        for (int f = 0; f < 4; ++f) acc[i][f] = 0ull;

    const float* xg = x + (size_t)kbase + (size_t)xkq * 4;

#define LOAD_CHUNK(kc, buf)                                                        \
    {                                                                              \
        int kb_ = (kc) * KCH;                                                      \
        _Pragma("unroll")                                                          \
        for (int s_ = 0; s_ < 8; ++s_) {                                           \
            int nl_ = xnl + 32 * s_;                                               \
            int node_ = nodeBase + nl_; if (node_ >= NN) node_ = NN - 1;           \
            unsigned d_ = (unsigned)__cvta_generic_to_shared(&xs[buf][nl_ * 5 + xkq]); \
            CPA16(d_, xg + (size_t)node_ * FIN + kb_);                             \
        }                                                                          \
        if (tid < 64) {                                                            \
            unsigned dw_ = (unsigned)__cvta_generic_to_shared(&wsm[buf][tid * 2]); \
            CPA16(dw_, &g_wz[half * 2048 + (kc) * 128 + tid * 2]);                 \
        }                                                                          \
        CP_COMMIT();                                                               \
    }

    LOAD_CHUNK(0, 0)

    for (int kc = 0; kc < NCHUNK_H; ++kc) {
        int cur = kc & 1;
        if (kc + 1 < NCHUNK_H) {
            LOAD_CHUNK(kc + 1, cur ^ 1)
            CP_WAIT(1);
        } else {
            CP_WAIT(0);
        }
        __syncthreads();

#pragma unroll
        for (int kq = 0; kq < 4; ++kq) {
            ulonglong2 w0a = *(const ulonglong2*)&wsm[cur][(2 * kq) * 16 + 4 * fg];
            ulonglong2 w0b = *(const ulonglong2*)&wsm[cur][(2 * kq) * 16 + 4 * fg + 2];
            ulonglong2 w1a = *(const ulonglong2*)&wsm[cur][(2 * kq + 1) * 16 + 4 * fg];
            ulonglong2 w1b = *(const ulonglong2*)&wsm[cur][(2 * kq + 1) * 16 + 4 * fg + 2];
#pragma unroll
            for (int i = 0; i < 8; ++i) {
                ulonglong2 xu = *(const ulonglong2*)&xs[cur][(ng + 32 * i) * 5 + kq];
                FMA2(acc[i][0], xu.x, w0a.x);
                FMA2(acc[i][1], xu.x, w0a.y);
                FMA2(acc[i][2], xu.x, w0b.x);
                FMA2(acc[i][3], xu.x, w0b.y);
                FMA2(acc[i][0], xu.y, w1a.x);
                FMA2(acc[i][1], xu.y, w1a.y);
                FMA2(acc[i][2], xu.y, w1b.x);
                FMA2(acc[i][3], xu.y, w1b.y);
            }
        }
        __syncthreads();
    }

    float4* dst = g_h1p + (size_t)half * NN * 4;
#pragma unroll
    for (int i = 0; i < 8; ++i) {
        int node = nodeBase + ng + 32 * i;
        if (node >= NN) continue;
        float lo, hi;
        float4 o;
        asm("mov.b64 {%0, %1}, %2;" : "=f"(lo), "=f"(hi) : "l"(acc[i][0])); o.x = lo + hi;
        asm("mov.b64 {%0, %1}, %2;" : "=f"(lo), "=f"(hi) : "l"(acc[i][1])); o.y = lo + hi;
        asm("mov.b64 {%0, %1}, %2;" : "=f"(lo), "=f"(hi) : "l"(acc[i][2])); o.z = lo + hi;
        asm("mov.b64 {%0, %1}, %2;" : "=f"(lo), "=f"(hi) : "l"(acc[i][3])); o.w = lo + hi;
        dst[node * 4 + fg] = o;
    }
}

// ---------------- 2-kernel scan front (block scan + block-sum scan) -----------
__global__ void scanA_kernel() {
    __shared__ int s[256];
    int tid = threadIdx.x;
    int i = blockIdx.x * 256 + tid;
    int v = (i < NN) ? g_cnt[i] : 0;
    s[tid] = v;
    __syncthreads();
    for (int off = 1; off < 256; off <<= 1) {
        int t = (tid >= off) ? s[tid - off] : 0;
        __syncthreads();
        s[tid] += t;
        __syncthreads();
    }
    if (i < NN) g_base[i] = s[tid] - v;          // exclusive, intra-block
    if (tid == 255) g_bsum[blockIdx.x] = s[255];
}

__global__ void scanB_kernel() {
    __shared__ int s[512];
    int tid = threadIdx.x;
    int v = (tid < NB) ? g_bsum[tid] : 0;
    s[tid] = v;
    __syncthreads();
    for (int off = 1; off < 512; off <<= 1) {
        int t = (tid >= off) ? s[tid - off] : 0;
        __syncthreads();
        s[tid] += t;
        __syncthreads();
    }
    if (tid < NB) g_bsumx[tid] = s[tid] - v;     // exclusive block offsets
}

// ---------------- scanC + combine K-split partials + dis ----------------------
__global__ void combine_kernel() {
    int i = blockIdx.x * blockDim.x + threadIdx.x;
    if (i < NN * 4) {
        float4 a = g_h1p[i];
        float4 b = g_h1p[NN * 4 + i];
        g_h1[i] = make_float4(a.x + b.x, a.y + b.y, a.z + b.z, a.w + b.w);
    }
    if (i < NN) {
        g_base[i] += g_bsumx[i >> 8];
        float d = g_deg[i];
        g_dis[i] = (d > 0.f) ? rsqrtf(d) : 0.f;
    }
}

// ---------------- scatter edges (src, norm); bumps g_base to row-end ----------
__global__ void scatter_kernel(const int* __restrict__ ei,
                               const float* __restrict__ w) {
    int e = blockIdx.x * blockDim.x + threadIdx.x;
    if (e >= EE) return;
    int r = ei[e];
    int c = ei[EE + e];
    float nw = g_dis[r] * w[e] * g_dis[c];
    int pos = atomicAdd(&g_base[c], 1);
    g_edge[pos] = make_int2(r, __float_as_int(nw));
}

// ---------------- gather-reduce propagation (warp per node, no atomics) -------
__global__ void __launch_bounds__(256) gather1_kernel() {
    int node = (blockIdx.x * 256 + threadIdx.x) >> 5;
    if (node >= NN) return;
    int lane = threadIdx.x & 31;
    int q = lane & 3;
    int es = lane >> 2;
    int b0 = node ? g_base[node - 1] : 0;
    int b1e = g_base[node];
    float4 acc = make_float4(0.f, 0.f, 0.f, 0.f);
    for (int i = b0 + es; i < b1e; i += 8) {
        int2 ew = g_edge[i];
        float nw = __int_as_float(ew.y);
        float4 v = g_h1[ew.x * 4 + q];
        acc.x += nw * v.x; acc.y += nw * v.y;
        acc.z += nw * v.z; acc.w += nw * v.w;
    }
#pragma unroll
    for (int m = 16; m >= 4; m >>= 1) {
        acc.x += __shfl_xor_sync(0xffffffffu, acc.x, m);
        acc.y += __shfl_xor_sync(0xffffffffu, acc.y, m);
        acc.z += __shfl_xor_sync(0xffffffffu, acc.z, m);
        acc.w += __shfl_xor_sync(0xffffffffu, acc.w, m);
    }
    if (es == 0) g_agg1[node * 4 + q] = acc;
}

// ---------------- fused layer-2 gather + W2 + log_softmax ---------------------
__global__ void __launch_bounds__(256) gather2out_kernel(const float* __restrict__ b1,
                                                         const float* __restrict__ W2,
                                                         const float* __restrict__ b2,
                                                         float* __restrict__ out) {
    __shared__ float w2s[HID * CC];
    __shared__ float b2s[CC];
    int tid = threadIdx.x;
    for (int i = tid; i < HID * CC; i += 256) w2s[i] = W2[i];
    if (tid < CC) b2s[tid] = b2[tid];
    __syncthreads();

    int node = (blockIdx.x * 256 + tid) >> 5;
    int lane = tid & 31;
    int q = lane & 3;
    int es = lane >> 2;
    float4 b = ((const float4*)b1)[q];
    int b0 = node ? g_base[node - 1] : 0;
    int b1e = g_base[node];
    float4 acc = make_float4(0.f, 0.f, 0.f, 0.f);
    for (int i = b0 + es; i < b1e; i += 8) {
        int2 ew = g_edge[i];
        float nw = __int_as_float(ew.y);
        float4 v = g_agg1[ew.x * 4 + q];
        acc.x += nw * fmaxf(v.x + b.x, 0.f);
        acc.y += nw * fmaxf(v.y + b.y, 0.f);
        acc.z += nw * fmaxf(v.z + b.z, 0.f);
        acc.w += nw * fmaxf(v.w + b.w, 0.f);
    }
#pragma unroll
    for (int m = 16; m >= 4; m >>= 1) {
        acc.x += __shfl_xor_sync(0xffffffffu, acc.x, m);
        acc.y += __shfl_xor_sync(0xffffffffu, acc.y, m);
        acc.z += __shfl_xor_sync(0xffffffffu, acc.z, m);
        acc.w += __shfl_xor_sync(0xffffffffu, acc.w, m);
    }
    // lanes 0..3 hold agg2 quarter q = lane; broadcast all 16 dims warp-wide
    float a[16];
#pragma unroll
    for (int j = 0; j < 4; ++j) {
        a[4 * j + 0] = __shfl_sync(0xffffffffu, acc.x, j);
        a[4 * j + 1] = __shfl_sync(0xffffffffu, acc.y, j);
        a[4 * j + 2] = __shfl_sync(0xffffffffu, acc.z, j);
        a[4 * j + 3] = __shfl_sync(0xffffffffu, acc.w, j);
    }
    // logits: lane c and (lanes 0..7) 32+c
    float l0 = b2s[lane];
#pragma unroll
    for (int i = 0; i < 16; ++i) l0 += a[i] * w2s[i * CC + lane];
    float l1 = -1e30f;
    if (lane < 8) {
        l1 = b2s[32 + lane];
#pragma unroll
        for (int i = 0; i < 16; ++i) l1 += a[i] * w2s[i * CC + 32 + lane];
    }
    float mx = fmaxf(l0, l1);
#pragma unroll
    for (int m = 16; m >= 1; m >>= 1) mx = fmaxf(mx, __shfl_xor_sync(0xffffffffu, mx, m));
    float s = expf(l0 - mx) + ((lane < 8) ? expf(l1 - mx) : 0.f);
#pragma unroll
    for (int m = 16; m >= 1; m >>= 1) s += __shfl_xor_sync(0xffffffffu, s, m);
    float lse = mx + logf(s);
    out[(size_t)node * CC + lane] = l0 - lse;
    if (lane < 8) out[(size_t)node * CC + 32 + lane] = l1 - lse;
}

// ---------------- launch ------------------------------------------------------
extern "C" void kernel_launch(void* const* d_in, const int* in_sizes, int n_in,
                              void* d_out, int out_size) {
    const float* x  = (const float*)d_in[0];
    const int*   ei = (const int*)d_in[1];
    const float* w  = (const float*)d_in[2];
    const float* W1 = (const float*)d_in[3];
    const float* b1 = (const float*)d_in[4];
    const float* W2 = (const float*)d_in[5];
    const float* b2 = (const float*)d_in[6];
    float*       out = (float*)d_out;

    zerowzip_kernel<<<(NN + 255) / 256, 256>>>(W1);
    mega_kernel<<<1564, 128>>>(x, ei, w);            // gemm1 (even) + count (odd)
    scanA_kernel<<<NB, 256>>>();
    scanB_kernel<<<1, 512>>>();
    combine_kernel<<<(NN * 4 + 255) / 256, 256>>>(); // scanC + h1 combine + dis
    scatter_kernel<<<(EE + 255) / 256, 256>>>(ei, w);
    gather1_kernel<<<(NN * 32 + 255) / 256, 256>>>();
    gather2out_kernel<<<(NN * 32 + 255) / 256, 256>>>(b1, W2, b2, out);
}